// round 3
// baseline (speedup 1.0000x reference)
#include <cuda_runtime.h>
#include <math.h>

#define NEL 32
#define NUP 16
#define NI  32
#define NL  16
#define NK  16
#define H1  128
#define H2  4
#define FLEN 392
#define GRID 128

__device__ float g_sh[2][NEL][H1];
__device__ float g_dh[2][NEL][NEL][H2];
__device__ float g_rN[NEL][NI];
__device__ float g_phi[NK][2][16][16];
__device__ float g_det[NK][2];
__device__ unsigned g_bar[NL + 2];

__device__ __forceinline__ unsigned ld_acq(const unsigned* p) {
    unsigned v;
    asm volatile("ld.acquire.gpu.global.u32 %0, [%1];" : "=r"(v) : "l"(p) : "memory");
    return v;
}
__device__ __forceinline__ void red_rel_add1(unsigned* p) {
    asm volatile("red.release.gpu.global.add.u32 [%0], 1;" :: "l"(p) : "memory");
}
__device__ __forceinline__ void bar_arrive(int idx) {
    __syncthreads();
    if (threadIdx.x == 0) red_rel_add1(&g_bar[idx]);
}
__device__ __forceinline__ void bar_wait(int idx, unsigned target) {
    if (threadIdx.x == 0) {
        while (ld_acq(&g_bar[idx]) < target) __nanosleep(32);
    }
    __syncthreads();
}

__global__ void pre_kernel(const float* __restrict__ ep,
                           const float* __restrict__ nuc) {
    int t = threadIdx.x;
    if (t < NL + 2) g_bar[t] = 0;
    for (int p = t; p < NEL * NI; p += blockDim.x) {
        int j = p >> 5, m = p & 31;
        float dx = ep[j * 3 + 0] - nuc[m * 3 + 0];
        float dy = ep[j * 3 + 1] - nuc[m * 3 + 1];
        float dz = ep[j * 3 + 2] - nuc[m * 3 + 2];
        float r  = sqrtf(dx * dx + dy * dy + dz * dz);
        g_sh[0][j][m * 3 + 0] = dx;
        g_sh[0][j][m * 3 + 1] = dy;
        g_sh[0][j][m * 3 + 2] = dz;
        g_sh[0][j][3 * NI + m] = r;
        g_rN[j][m] = r;
    }
    for (int p = t; p < NEL * NEL; p += blockDim.x) {
        int i = p >> 5, j = p & 31;
        float dx = ep[i * 3 + 0] - ep[j * 3 + 0];
        float dy = ep[i * 3 + 1] - ep[j * 3 + 1];
        float dz = ep[i * 3 + 2] - ep[j * 3 + 2];
        float r  = sqrtf(dx * dx + dy * dy + dz * dz);
        g_dh[0][i][j][0] = dx;
        g_dh[0][i][j][1] = dy;
        g_dh[0][i][j][2] = dz;
        g_dh[0][i][j][3] = r;
    }
}

__device__ __forceinline__ void prefetch_layer(
    int l, int n, int og, int c4, int fs, int t,
    const float* __restrict__ v, const float* __restrict__ b,
    const float* __restrict__ w, const float* __restrict__ c,
    float4 (&wr)[13], float4& bias, float4 (&dw)[5])
{
    const float* vp = v + (((size_t)l * NEL + n) * FLEN) * H1 + og * 32 + c4 * 4;
#pragma unroll
    for (int i = 0; i < 12; i++)
        wr[i] = *reinterpret_cast<const float4*>(vp + (size_t)(fs + 32 * i) * H1);
    if (fs < 8)
        wr[12] = *reinterpret_cast<const float4*>(vp + (size_t)(fs + 384) * H1);
    if (t < 8) {
        bias = *reinterpret_cast<const float4*>(
            b + ((size_t)l * NEL + n) * H1 + og * 32 + t * 4);
        if (l < NL - 1) {
            const int dj = og * 8 + t;
            const float* wp = w + ((size_t)(l * NEL + n) * NEL + dj) * 16;
            dw[0] = *reinterpret_cast<const float4*>(wp);
            dw[1] = *reinterpret_cast<const float4*>(wp + 4);
            dw[2] = *reinterpret_cast<const float4*>(wp + 8);
            dw[3] = *reinterpret_cast<const float4*>(wp + 12);
            dw[4] = *reinterpret_cast<const float4*>(
                c + ((size_t)(l * NEL + n) * NEL + dj) * 4);
        }
    }
}

__device__ __forceinline__ void layer_step(
    int l, int n, int og, int c4, int fs, int t, int lane, int wrp,
    const float* __restrict__ v, const float* __restrict__ b,
    const float* __restrict__ w, const float* __restrict__ c,
    float4 (&wr)[13], float4& bias, float4 (&dw)[5],
    float4 (&wrN)[13], float4& biasN, float4 (&dwN)[5],
    float* fsh, float4 (*part)[8])
{
    if (l > 0) bar_wait(l - 1, GRID);
    const int cur = l & 1, nxt = cur ^ 1;

    if (t < H1) {
        float s = 0.f;
#pragma unroll
        for (int r = 0; r < NUP; r++) s += __ldcg(&g_sh[cur][r][t]);
        fsh[H1 + t] = s * (1.0f / NUP);
        fsh[t] = __ldcg(&g_sh[cur][n][t]);
    } else {
        int o = t - H1;
        float s = 0.f;
#pragma unroll
        for (int r = NUP; r < NEL; r++) s += __ldcg(&g_sh[cur][r][o]);
        fsh[2 * H1 + o] = s * (1.0f / 16);
    }
    if (t < 8) {
        int d  = t & 3;
        int j0 = (t < 4) ? 0 : 16;
        float s = 0.f;
#pragma unroll
        for (int jj = 0; jj < 16; jj++) s += __ldcg(&g_dh[cur][n][j0 + jj][d]);
        fsh[3 * H1 + (t < 4 ? 0 : 4) + d] = s * (1.0f / 16);
    }
    __syncthreads();

    float4 acc = make_float4(0.f, 0.f, 0.f, 0.f);
#pragma unroll
    for (int i = 0; i < 12; i++) {
        float s = fsh[fs + 32 * i];
        acc.x += s * wr[i].x; acc.y += s * wr[i].y;
        acc.z += s * wr[i].z; acc.w += s * wr[i].w;
    }
    if (fs < 8) {
        float s = fsh[fs + 384];
        acc.x += s * wr[12].x; acc.y += s * wr[12].y;
        acc.z += s * wr[12].z; acc.w += s * wr[12].w;
    }

    const int dj = og * 8 + t;
    float4 od;
    const bool do_d = (t < 8) && (l < NL - 1);
    if (do_d) {
        float4 d4 = __ldcg(reinterpret_cast<const float4*>(&g_dh[cur][n][dj][0]));
        float o0 = d4.x * dw[0].x + d4.y * dw[1].x + d4.z * dw[2].x + d4.w * dw[3].x;
        float o1 = d4.x * dw[0].y + d4.y * dw[1].y + d4.z * dw[2].y + d4.w * dw[3].y;
        float o2 = d4.x * dw[0].z + d4.y * dw[1].z + d4.z * dw[2].z + d4.w * dw[3].z;
        float o3 = d4.x * dw[0].w + d4.y * dw[1].w + d4.z * dw[2].w + d4.w * dw[3].w;
        od.x = tanhf(o0 + dw[4].x) + d4.x;
        od.y = tanhf(o1 + dw[4].y) + d4.y;
        od.z = tanhf(o2 + dw[4].z) + d4.z;
        od.w = tanhf(o3 + dw[4].w) + d4.w;
    }

    if (l + 1 < NL)
        prefetch_layer(l + 1, n, og, c4, fs, t, v, b, w, c, wrN, biasN, dwN);

#pragma unroll
    for (int off = 16; off >= 8; off >>= 1) {
        acc.x += __shfl_down_sync(0xffffffffu, acc.x, off);
        acc.y += __shfl_down_sync(0xffffffffu, acc.y, off);
        acc.z += __shfl_down_sync(0xffffffffu, acc.z, off);
        acc.w += __shfl_down_sync(0xffffffffu, acc.w, off);
    }
    if (lane < 8) part[wrp][lane] = acc;
    __syncthreads();

    if (t < 8) {
        float4 a = part[0][t];
#pragma unroll
        for (int ww = 1; ww < 8; ww++) {
            a.x += part[ww][t].x; a.y += part[ww][t].y;
            a.z += part[ww][t].z; a.w += part[ww][t].w;
        }
        int o = og * 32 + t * 4;
        a.x = tanhf(a.x + bias.x) + fsh[o + 0];
        a.y = tanhf(a.y + bias.y) + fsh[o + 1];
        a.z = tanhf(a.z + bias.z) + fsh[o + 2];
        a.w = tanhf(a.w + bias.w) + fsh[o + 3];
        __stcg(reinterpret_cast<float4*>(&g_sh[nxt][n][o]), a);
    }
    if (do_d)
        __stcg(reinterpret_cast<float4*>(&g_dh[nxt][n][dj][0]), od);

    bar_arrive(l);
}

__global__ void __launch_bounds__(256, 1) fused_kernel(
    const float* __restrict__ v,  const float* __restrict__ b,
    const float* __restrict__ w,  const float* __restrict__ c,
    const float* __restrict__ fw, const float* __restrict__ fb,
    const float* __restrict__ pi, const float* __restrict__ sigma,
    const float* __restrict__ omega, float* __restrict__ out)
{
    __shared__ float  fsh[FLEN];
    __shared__ float4 part[8][8];
    __shared__ float  A[16][17];
    __shared__ float  fac[16];
    __shared__ int    pivs;
    __shared__ float  dsh;

    const int t    = threadIdx.x;
    const int n    = blockIdx.x >> 2;
    const int og   = blockIdx.x & 3;
    const int c4   = t & 7;
    const int fs   = t >> 3;
    const int lane = t & 31, wrp = t >> 5;

    float4 wrA[13], wrB[13];
    float4 biasA, biasB;
    float4 dwA[5], dwB[5];

    prefetch_layer(0, n, og, c4, fs, t, v, b, w, c, wrA, biasA, dwA);
#pragma unroll 1
    for (int lp = 0; lp < NL; lp += 2) {
        layer_step(lp,     n, og, c4, fs, t, lane, wrp, v, b, w, c,
                   wrA, biasA, dwA, wrB, biasB, dwB, fsh, part);
        layer_step(lp + 1, n, og, c4, fs, t, lane, wrp, v, b, w, c,
                   wrB, biasB, dwB, wrA, biasA, dwA, fsh, part);
    }

    // ---- phi (needs all blocks' final activations) ----
    bar_wait(NL - 1, GRID);
    {
        const int k    = blockIdx.x >> 3;
        const int i    = (blockIdx.x & 7) * 4 + (t >> 6);
        const int spin = i >> 4;
        const int tl   = t & 63;
        const int jl   = tl >> 2, s = tl & 3;
        const int j    = spin * 16 + jl;
        const float* fwp = fw + (size_t)(k * NEL + i) * H1;
        float dot = 0.f;
#pragma unroll
        for (int q = 0; q < 32; q++)
            dot += fwp[s + 4 * q] * __ldcg(&g_sh[0][j][s + 4 * q]);
        const float* pip = pi    + (size_t)(k * NEL + i) * NI;
        const float* sgp = sigma + (size_t)(k * NEL + i) * NI;
        float env = 0.f;
#pragma unroll
        for (int q = 0; q < 8; q++) {
            int m = s * 8 + q;
            env += pip[m] * __expf(-fabsf(sgp[m]) * g_rN[j][m]);
        }
        dot += __shfl_down_sync(0xffffffffu, dot, 2, 4);
        dot += __shfl_down_sync(0xffffffffu, dot, 1, 4);
        env += __shfl_down_sync(0xffffffffu, env, 2, 4);
        env += __shfl_down_sync(0xffffffffu, env, 1, 4);
        if (s == 0)
            __stcg(&g_phi[k][spin][i & 15][jl], (dot + fb[k * NEL + i]) * env);
    }
    bar_arrive(NL);

    if (blockIdx.x < 32) {
        bar_wait(NL, GRID);
        const int k = blockIdx.x >> 1, spin = blockIdx.x & 1;
        const int r = t >> 4, cc = t & 15;
        A[r][cc] = __ldcg(&g_phi[k][spin][r][cc]);
        if (t == 0) dsh = 1.0f;
        __syncthreads();
        for (int p = 0; p < 16; p++) {
            if (t == 0) {
                int best = p;
                float bv = fabsf(A[p][p]);
                for (int rr = p + 1; rr < 16; rr++) {
                    float v2 = fabsf(A[rr][p]);
                    if (v2 > bv) { bv = v2; best = rr; }
                }
                pivs = best;
                if (best != p) dsh = -dsh;
            }
            __syncthreads();
            int piv = pivs;
            if (piv != p && t < 16) {
                float tmp = A[p][t]; A[p][t] = A[piv][t]; A[piv][t] = tmp;
            }
            __syncthreads();
            if (t < 16 && t > p) fac[t] = A[t][p] / A[p][p];
            if (t == 0) dsh *= A[p][p];
            __syncthreads();
            if (r > p && cc > p) A[r][cc] -= fac[r] * A[p][cc];
            __syncthreads();
        }
        if (t == 0) __stcg(&g_det[k][spin], dsh);
        bar_arrive(NL + 1);
    }

    if (blockIdx.x == 0) {
        bar_wait(NL + 1, 32);
        if (t < 32) {
            float vv = (t < NK) ? omega[t] * __ldcg(&g_det[t][0]) * __ldcg(&g_det[t][1])
                                : 0.0f;
#pragma unroll
            for (int off = 16; off; off >>= 1)
                vv += __shfl_down_sync(0xffffffffu, vv, off);
            if (t == 0) out[0] = vv;
        }
    }
}

extern "C" void kernel_launch(void* const* d_in, const int* in_sizes, int n_in,
                              void* d_out, int out_size) {
    const float* ep    = (const float*)d_in[0];
    const float* nuc   = (const float*)d_in[1];
    const float* v     = (const float*)d_in[2];
    const float* b     = (const float*)d_in[3];
    const float* w     = (const float*)d_in[4];
    const float* c     = (const float*)d_in[5];
    const float* fw    = (const float*)d_in[6];
    const float* fb    = (const float*)d_in[7];
    const float* pi    = (const float*)d_in[8];
    const float* sigma = (const float*)d_in[9];
    const float* omega = (const float*)d_in[10];

    pre_kernel<<<1, 256>>>(ep, nuc);
    fused_kernel<<<GRID, 256>>>(v, b, w, c, fw, fb, pi, sigma, omega, (float*)d_out);
}